// round 6
// baseline (speedup 1.0000x reference)
#include <cuda_runtime.h>
#include <math.h>

#define N 8192
#define D 64
#define ALPHA 0.2f
#define NB 4096          // value bins
#define NCHUNK 64
#define CHUNK 128        // N / NCHUNK
#define GRID1 128        // blocks in fused feat+bucket kernel

// ---------------- scratch ----------------
__device__ float g_h[N * D];
__device__ float g_f1[N];
__device__ float g_f2[N];
__device__ float g_fmin, g_fmax, g_scale;
__device__ int   g_binStart[NB + 1];
__device__ int   g_hist[NB];
__device__ int   g_cur[NB];
__device__ float g_f2s[N];          // bucket-sorted f2 (by (bin, orig idx))
__device__ int   g_idx[N];
__device__ float g_p[N];            // e^{f2-fmax}
__device__ float g_q[N];            // e^{a(f2-fmax)}
__device__ float g_csumP[NCHUNK * D];
__device__ float g_csumQ[NCHUNK * D];
__device__ float g_csp[NCHUNK], g_csq[NCHUNK];
__device__ float g_Cpos[(N + 1) * D];   // inclusive suffix of p*h
__device__ float g_Cneg[(N + 1) * D];   // exclusive prefix of q*h
__device__ float g_Dpos[N + 1], g_Dneg[N + 1];

// monotone-encoded float extrema (reset in-kernel each run)
__device__ unsigned g_encmax = 0u;
__device__ unsigned g_encmin = 0xFFFFFFFFu;

// grid barrier counters (self-resetting: arrive + exit pairs)
__device__ int g_ba[4] = {0, 0, 0, 0};
__device__ int g_bx[4] = {0, 0, 0, 0};
__device__ int g_c2 = 0;
__device__ int g_c2done = 0;

__device__ __forceinline__ int bin_of(float v, float fmin, float scale) {
    int b = (int)((v - fmin) * scale);
    return b < 0 ? 0 : (b > NB - 1 ? NB - 1 : b);
}
__device__ __forceinline__ unsigned enc_f(float f) {
    unsigned u = __float_as_uint(f);
    return (u & 0x80000000u) ? ~u : (u | 0x80000000u);
}
__device__ __forceinline__ float dec_f(unsigned e) {
    return (e & 0x80000000u) ? __uint_as_float(e & 0x7FFFFFFFu) : __uint_as_float(~e);
}
__device__ __forceinline__ void gbar(int idx, int nb) {
    __syncthreads();
    __threadfence();
    if (threadIdx.x == 0) {
        atomicAdd(&g_ba[idx], 1);
        while (atomicAdd(&g_ba[idx], 0) < nb) __nanosleep(128);
        int d = atomicAdd(&g_bx[idx], 1);
        if (d == nb - 1) { atomicExch(&g_ba[idx], 0); atomicExch(&g_bx[idx], 0); }
    }
    __syncthreads();
}

// =============== K1: feat (128 blocks) + distributed bucket ===============
// 128 blocks x 1024 threads
__global__ void k_feat_bucket(const float* __restrict__ x, const float* __restrict__ Wt,
                              const float* __restrict__ a1, const float* __restrict__ b1,
                              const float* __restrict__ a2, const float* __restrict__ b2) {
    __shared__ float sW[D * D];
    __shared__ float sx[16 * D];
    __shared__ float s12[64];
    __shared__ int swsum[32];
    __shared__ float sconst[4];      // fmin, fmax, scale

    int t = threadIdx.x;
    int row_base = blockIdx.x * 64;

    // zero this block's histogram slice (visible by barrier 1's fence)
    if (t < 32) g_hist[blockIdx.x * 32 + t] = 0;

    // ---------------- feat phase ----------------
    {
        int r = t >> 6;              // 0..15
        int o = t & 63;
#pragma unroll
        for (int u = 0; u < 4; u++) sW[t + u * 1024] = Wt[t + u * 1024];
        float A1 = a1[o], A2 = a2[o];
        float B1 = b1[0], B2 = b2[0];

        float xv = x[(row_base + r) * D + o];

        for (int it = 0; it < 4; it++) {
            int row = row_base + it * 16 + r;
            __syncthreads();
            sx[r * 64 + o] = xv;
            __syncthreads();
            if (it < 3) xv = x[(row + 16) * D + o];

            float h = 0.f;
#pragma unroll
            for (int i = 0; i < D; i++) h = fmaf(sx[r * 64 + i], sW[i * 64 + o], h);
            g_h[row * D + o] = h;

            float v1 = h * A1;
            float v2 = h * A2;
#pragma unroll
            for (int s = 16; s; s >>= 1) {
                v1 += __shfl_xor_sync(0xFFFFFFFFu, v1, s);
                v2 += __shfl_xor_sync(0xFFFFFFFFu, v2, s);
            }
            int w = t >> 5;
            if ((t & 31) == 0) { s12[w] = v1; s12[32 + w] = v2; }
            __syncthreads();
            if (o == 0) {
                g_f1[row] = s12[2 * r] + s12[2 * r + 1] + B1;
                g_f2[row] = s12[32 + 2 * r] + s12[32 + 2 * r + 1] + B2;
            }
        }
    }
    __syncthreads();

    // ---------------- local min/max -> global encoded atomics ----------------
    float myf2 = 0.f;
    if (t < 64) {
        myf2 = g_f2[row_base + t];   // own block's writes: visible after syncthreads
        float mx = myf2, mn = myf2;
#pragma unroll
        for (int s = 16; s; s >>= 1) {
            mx = fmaxf(mx, __shfl_xor_sync(0xFFFFFFFFu, mx, s));
            mn = fminf(mn, __shfl_xor_sync(0xFFFFFFFFu, mn, s));
        }
        if ((t & 31) == 0) {
            atomicMax(&g_encmax, enc_f(mx));
            atomicMin(&g_encmin, enc_f(mn));
        }
    }

    gbar(0, GRID1);                  // all f2 + extrema done

    // one thread per block reads extrema (2 atomic reads/block), broadcasts via smem
    if (t == 0) {
        float fmax = dec_f(atomicAdd(&g_encmax, 0u));
        float fmin = dec_f(atomicAdd(&g_encmin, 0u));
        float scale = (float)NB / fmaxf(fmax - fmin, 1e-20f);
        sconst[0] = fmin; sconst[1] = fmax; sconst[2] = scale;
        if (blockIdx.x == 0) { g_fmin = fmin; g_fmax = fmax; g_scale = scale; }
    }
    __syncthreads();
    float fmin = sconst[0], scale = sconst[2];

    // ---------------- distributed histogram ----------------
    int mybin = 0;
    if (t < 64) {
        mybin = bin_of(myf2, fmin, scale);
        atomicAdd(&g_hist[mybin], 1);
    }

    gbar(1, GRID1);                  // hist complete

    // ---------------- block 0: scan hist -> binStart + cursors; reset extrema ----------------
    if (blockIdx.x == 0) {
        if (t == 0) { atomicExch(&g_encmax, 0u); atomicExch(&g_encmin, 0xFFFFFFFFu); }
        int h4[4];
        int base4 = t * 4;
        int sum = 0;
#pragma unroll
        for (int j = 0; j < 4; j++) { h4[j] = __ldcg(&g_hist[base4 + j]); sum += h4[j]; }
        int incl = sum;
#pragma unroll
        for (int s = 1; s < 32; s <<= 1) {
            int v = __shfl_up_sync(0xFFFFFFFFu, incl, s);
            if ((t & 31) >= s) incl += v;
        }
        if ((t & 31) == 31) swsum[t >> 5] = incl;
        __syncthreads();
        if (t < 32) {
            int v = swsum[t];
            int inc = v;
#pragma unroll
            for (int s = 1; s < 32; s <<= 1) {
                int u = __shfl_up_sync(0xFFFFFFFFu, inc, s);
                if (t >= s) inc += u;
            }
            swsum[t] = inc - v;
        }
        __syncthreads();
        int run = swsum[t >> 5] + (incl - sum);
#pragma unroll
        for (int j = 0; j < 4; j++) {
            g_binStart[base4 + j] = run;
            g_cur[base4 + j] = run;
            run += h4[j];
        }
        if (t == 0) g_binStart[NB] = N;
    }

    gbar(2, GRID1);                  // binStart + cursors ready

    // ---------------- distributed scatter ----------------
    if (t < 64) {
        int pos = atomicAdd(&g_cur[mybin], 1);
        g_f2s[pos] = myf2;
        g_idx[pos] = row_base + t;
    }

    gbar(3, GRID1);                  // scatter complete

    // ---------------- per-bin sort by original index (determinism) ----------------
    int gt = blockIdx.x * 1024 + t;
    if (gt < NB) {
        int s0 = __ldcg(&g_binStart[gt]);
        int e0 = __ldcg(&g_binStart[gt + 1]);
        for (int i = s0 + 1; i < e0; i++) {
            int ki = __ldcg(&g_idx[i]); float kf = __ldcg(&g_f2s[i]);
            int j = i - 1;
            while (j >= s0) {
                int vj = __ldcg(&g_idx[j]);
                if (vj <= ki) break;
                g_idx[j + 1] = vj; g_f2s[j + 1] = __ldcg(&g_f2s[j]); j--;
            }
            g_idx[j + 1] = ki; g_f2s[j + 1] = kf;
        }
    }
}

// =============== K2: chunk sums + grid barrier + prefix/suffix walk ===============
// NCHUNK blocks x 256 threads; dyn smem: sPc[8192] | sQc[8192] | sps[128] | sqs[128]
__global__ void k_scanfused() {
    extern __shared__ float sm2[];
    float* sPc = sm2;                       // CHUNK*64
    float* sQc = sm2 + CHUNK * 64;          // CHUNK*64
    float* sps = sm2 + 2 * CHUNK * 64;      // CHUNK
    float* sqs = sps + CHUNK;               // CHUNK
    __shared__ float sP[4][64], sQ[4][64], sw[8];

    int t = threadIdx.x;
    int o = t & 63, r = t >> 6;
    int chunk = blockIdx.x;
    int k0 = chunk * CHUNK;

    // ---- phase A: p/q + gather + P/Q into smem + chunk sums ----
    float fmax = g_fmax;
    if (t < CHUNK) {
        float d = g_f2s[k0 + t] - fmax;
        float pv = expf(d), qv = expf(ALPHA * d);
        sps[t] = pv; sqs[t] = qv;
        g_p[k0 + t] = pv; g_q[k0 + t] = qv;
    }
    __syncthreads();

    float aP = 0.f, aQ = 0.f;
#pragma unroll 8
    for (int m = r; m < CHUNK; m += 4) {
        int k = k0 + m;
        float hv = g_h[g_idx[k] * D + o];
        float Pv = sps[m] * hv;
        float Qv = sqs[m] * hv;
        sPc[m * 64 + o] = Pv;
        sQc[m * 64 + o] = Qv;
        aP += Pv; aQ += Qv;
    }
    sP[r][o] = aP; sQ[r][o] = aQ;

    float spv = 0.f, sqv = 0.f;
    if (t < CHUNK) { spv = sps[t]; sqv = sqs[t]; }
#pragma unroll
    for (int s = 16; s; s >>= 1) {
        spv += __shfl_xor_sync(0xFFFFFFFFu, spv, s);
        sqv += __shfl_xor_sync(0xFFFFFFFFu, sqv, s);
    }
    if (t < CHUNK && (t & 31) == 0) { sw[t >> 5] = spv; sw[4 + (t >> 5)] = sqv; }
    __syncthreads();

    if (r == 0) {
        g_csumP[chunk * 64 + o] = sP[0][o] + sP[1][o] + sP[2][o] + sP[3][o];
        g_csumQ[chunk * 64 + o] = sQ[0][o] + sQ[1][o] + sQ[2][o] + sQ[3][o];
    }
    if (t == 0) {
        g_csp[chunk] = sw[0] + sw[1] + sw[2] + sw[3];
        g_csq[chunk] = sw[4] + sw[5] + sw[6] + sw[7];
    }

    // ---- grid barrier (all 64 blocks resident) ----
    __syncthreads();
    __threadfence();
    if (t == 0) {
        atomicAdd(&g_c2, 1);
        while (atomicAdd(&g_c2, 0) < NCHUNK) __nanosleep(64);
    }
    __syncthreads();

    // ---- phase B: offsets + walks (from smem) ----
    if (t < 64) {
        float off = 0.f;
#pragma unroll
        for (int c = 0; c < NCHUNK; c++) {
            float v = __ldcg(&g_csumQ[c * 64 + t]);
            if (c < chunk) off += v;
        }
        float run = off;
#pragma unroll 8
        for (int m = 0; m < CHUNK; m++) {
            g_Cneg[(size_t)(k0 + m) * D + t] = run;
            run += sQc[m * 64 + t];
        }
        if (chunk == NCHUNK - 1) g_Cneg[(size_t)N * D + t] = run;
    } else if (t < 128) {
        int c0 = t - 64;
        float off = 0.f;
#pragma unroll
        for (int c = 0; c < NCHUNK; c++) {
            float v = __ldcg(&g_csumP[c * 64 + c0]);
            if (c > chunk) off += v;
        }
        float run = off;
        if (chunk == NCHUNK - 1) g_Cpos[(size_t)N * D + c0] = 0.f;
#pragma unroll 8
        for (int m = CHUNK - 1; m >= 0; m--) {
            run += sPc[m * 64 + c0];
            g_Cpos[(size_t)(k0 + m) * D + c0] = run;
        }
    } else if (t == 128) {
        float off = 0.f;
#pragma unroll
        for (int c = 0; c < NCHUNK; c++) { float v = __ldcg(&g_csq[c]); if (c < chunk) off += v; }
        float run = off;
        for (int m = 0; m < CHUNK; m++) { g_Dneg[k0 + m] = run; run += sqs[m]; }
        if (chunk == NCHUNK - 1) g_Dneg[N] = run;
    } else if (t == 129) {
        float off = 0.f;
#pragma unroll
        for (int c = 0; c < NCHUNK; c++) { float v = __ldcg(&g_csp[c]); if (c > chunk) off += v; }
        float run = off;
        if (chunk == NCHUNK - 1) g_Dpos[N] = 0.f;
        for (int m = CHUNK - 1; m >= 0; m--) { run += sps[m]; g_Dpos[k0 + m] = run; }
    }

    // ---- replay-safe counter reset (last block out resets both) ----
    __syncthreads();
    if (t == 0) {
        int d = atomicAdd(&g_c2done, 1);
        if (d == NCHUNK - 1) {
            atomicExch(&g_c2, 0);
            atomicExch(&g_c2done, 0);
        }
    }
}

// =============== K3: per-row combine + exact boundary bin + ELU ===============
__global__ void k_out(float* __restrict__ out) {
    int t = threadIdx.x;                 // 256, 4 rows/block
    int row = blockIdx.x * 4 + (t >> 6);
    int o = t & 63;

    float f1 = g_f1[row];
    float fmax = g_fmax, fmin = g_fmin, scale = g_scale;
    float s0 = f1 + fmax;
    float m = (s0 >= 0.f) ? s0 : ALPHA * s0;
    float A = expf(s0 - m);
    float B = expf(ALPHA * s0 - m);
    float thr = -f1;

    int b = bin_of(thr, fmin, scale);
    int bs = g_binStart[b];
    int be = g_binStart[b + 1];

    float num = A * g_Cpos[(size_t)be * D + o] + B * g_Cneg[(size_t)bs * D + o];
    float den = A * g_Dpos[be] + B * g_Dneg[bs];

    for (int j = bs; j < be; j++) {      // exact compares within boundary bin
        float f2j = g_f2s[j];
        float hv = g_h[g_idx[j] * D + o];
        if (f2j >= thr) { float w = A * g_p[j]; num = fmaf(w, hv, num); den += w; }
        else            { float w = B * g_q[j]; num = fmaf(w, hv, num); den += w; }
    }

    float ret = num / den;
    out[row * D + o] = (ret > 0.f) ? ret : expm1f(ret);
}

// ---------------- launch ----------------
extern "C" void kernel_launch(void* const* d_in, const int* in_sizes, int n_in,
                              void* d_out, int out_size) {
    const float* x  = (const float*)d_in[0];
    const float* Wt = (const float*)d_in[1];
    const float* a1 = (const float*)d_in[2];
    const float* b1 = (const float*)d_in[3];
    const float* a2 = (const float*)d_in[4];
    const float* b2 = (const float*)d_in[5];
    float* out = (float*)d_out;

    const int smem_k2 = (2 * CHUNK * 64 + 2 * CHUNK) * 4;      // 66.5 KB

    static bool attr_set = false;
    if (!attr_set) {
        cudaFuncSetAttribute(k_scanfused, cudaFuncAttributeMaxDynamicSharedMemorySize, smem_k2);
        attr_set = true;
    }

    k_feat_bucket<<<GRID1, 1024>>>(x, Wt, a1, b1, a2, b2);
    k_scanfused<<<NCHUNK, 256, smem_k2>>>();
    k_out<<<2048, 256>>>(out);
}

// round 7
// speedup vs baseline: 2.1132x; 2.1132x over previous
#include <cuda_runtime.h>
#include <math.h>

#define N 8192
#define D 64
#define ALPHA 0.2f
#define NB 4096          // value bins
#define CAP 64           // member-list capacity per bin (avg occupancy = 2)
#define NBCH 32          // scan chunks
#define BCH 128          // bins per chunk

// ---------------- scratch ----------------
__device__ float g_h[N * D];
__device__ float g_f1[N];
__device__ float g_f2[N];
__device__ float g_fmin, g_fmax, g_scale;
__device__ float g_binP[NB * D];      // sum of p_j * h_j over bin
__device__ float g_binQ[NB * D];      // sum of q_j * h_j over bin
__device__ float g_bDp[NB], g_bDq[NB];
__device__ int   g_cnt[NB];
__device__ int   g_mIdx[NB * CAP];
__device__ float g_mF2[NB * CAP];
__device__ float g_csumP[NBCH * D], g_csumQ[NBCH * D];
__device__ float g_csp[NBCH], g_csq[NBCH];
__device__ float g_Cpos[(NB + 1) * D];   // inclusive suffix of binP
__device__ float g_Cneg[(NB + 1) * D];   // exclusive prefix of binQ
__device__ float g_Dpos[NB + 1], g_Dneg[NB + 1];

// monotone-encoded float extrema (reset in k_binscan after consumption)
__device__ unsigned g_encmax = 0u;
__device__ unsigned g_encmin = 0xFFFFFFFFu;

// scan-kernel barrier (self-resetting)
__device__ int g_c2 = 0;
__device__ int g_c2done = 0;

__device__ __forceinline__ int bin_of(float v, float fmin, float scale) {
    int b = (int)((v - fmin) * scale);
    return b < 0 ? 0 : (b > NB - 1 ? NB - 1 : b);
}
__device__ __forceinline__ unsigned enc_f(float f) {
    unsigned u = __float_as_uint(f);
    return (u & 0x80000000u) ? ~u : (u | 0x80000000u);
}
__device__ __forceinline__ float dec_f(unsigned e) {
    return (e & 0x80000000u) ? __uint_as_float(e & 0x7FFFFFFFu) : __uint_as_float(~e);
}

// =============== K1: feat + zero bin scratch + extrema ===============
// 128 blocks x 1024 threads, 64 rows/block
__global__ void k_feat(const float* __restrict__ x, const float* __restrict__ Wt,
                       const float* __restrict__ a1, const float* __restrict__ b1,
                       const float* __restrict__ a2, const float* __restrict__ b2) {
    __shared__ float sW[D * D];
    __shared__ float sx[16 * D];
    __shared__ float s12[64];

    int t = threadIdx.x;
    int row_base = blockIdx.x * 64;

    // zero this block's slice of bin scratch (consumed by K2 after kernel boundary)
    {
        float4 z = make_float4(0.f, 0.f, 0.f, 0.f);
        if (t < 512) {
            ((float4*)g_binP)[blockIdx.x * 512 + t] = z;
            ((float4*)g_binQ)[blockIdx.x * 512 + t] = z;
        }
        if (t < 32) {
            int i = blockIdx.x * 32 + t;
            g_cnt[i] = 0; g_bDp[i] = 0.f; g_bDq[i] = 0.f;
        }
    }

    // ---------------- feat ----------------
    {
        int r = t >> 6;              // 0..15
        int o = t & 63;
#pragma unroll
        for (int u = 0; u < 4; u++) sW[t + u * 1024] = Wt[t + u * 1024];
        float A1 = a1[o], A2 = a2[o];
        float B1 = b1[0], B2 = b2[0];

        float xv = x[(row_base + r) * D + o];

        for (int it = 0; it < 4; it++) {
            int row = row_base + it * 16 + r;
            __syncthreads();
            sx[r * 64 + o] = xv;
            __syncthreads();
            if (it < 3) xv = x[(row + 16) * D + o];

            float h = 0.f;
#pragma unroll
            for (int i = 0; i < D; i++) h = fmaf(sx[r * 64 + i], sW[i * 64 + o], h);
            g_h[row * D + o] = h;

            float v1 = h * A1;
            float v2 = h * A2;
#pragma unroll
            for (int s = 16; s; s >>= 1) {
                v1 += __shfl_xor_sync(0xFFFFFFFFu, v1, s);
                v2 += __shfl_xor_sync(0xFFFFFFFFu, v2, s);
            }
            int w = t >> 5;
            if ((t & 31) == 0) { s12[w] = v1; s12[32 + w] = v2; }
            __syncthreads();
            if (o == 0) {
                g_f1[row] = s12[2 * r] + s12[2 * r + 1] + B1;
                g_f2[row] = s12[32 + 2 * r] + s12[32 + 2 * r + 1] + B2;
            }
        }
    }
    __syncthreads();

    // extrema of this block's 64 f2 values (exact, order-independent)
    if (t < 64) {
        float v = g_f2[row_base + t];     // same-SM write -> L1 coherent
        float mx = v, mn = v;
#pragma unroll
        for (int s = 16; s; s >>= 1) {
            mx = fmaxf(mx, __shfl_xor_sync(0xFFFFFFFFu, mx, s));
            mn = fminf(mn, __shfl_xor_sync(0xFFFFFFFFu, mn, s));
        }
        if ((t & 31) == 0) {
            atomicMax(&g_encmax, enc_f(mx));
            atomicMin(&g_encmin, enc_f(mn));
        }
    }
}

// =============== K2: per-bin atomic aggregation ===============
// 64 blocks x 256 threads, 128 nodes/block
__global__ void k_binagg() {
    __shared__ int sbin[128];
    __shared__ float sp[128], sq[128];
    __shared__ float scons[4];

    int t = threadIdx.x;
    if (t == 0) {
        float fmax = dec_f(g_encmax);     // final after K1 (kernel boundary)
        float fmin = dec_f(g_encmin);
        float scale = (float)NB / fmaxf(fmax - fmin, 1e-20f);
        scons[0] = fmin; scons[1] = fmax; scons[2] = scale;
        if (blockIdx.x == 0) { g_fmin = fmin; g_fmax = fmax; g_scale = scale; }
    }
    __syncthreads();
    float fmin = scons[0], fmax = scons[1], scale = scons[2];

    int node0 = blockIdx.x * 128;
    if (t < 128) {
        int node = node0 + t;
        float f2 = g_f2[node];
        int b = bin_of(f2, fmin, scale);
        float d = f2 - fmax;
        float pv = expf(d), qv = expf(ALPHA * d);
        sbin[t] = b; sp[t] = pv; sq[t] = qv;
        atomicAdd(&g_bDp[b], pv);
        atomicAdd(&g_bDq[b], qv);
        int c = atomicAdd(&g_cnt[b], 1);
        if (c < CAP) { g_mIdx[b * CAP + c] = node; g_mF2[b * CAP + c] = f2; }
    }
    __syncthreads();

    int o = t & 63, r = t >> 6;
#pragma unroll 8
    for (int m = r; m < 128; m += 4) {
        float hv = g_h[(node0 + m) * D + o];          // coalesced (original order)
        atomicAdd(&g_binP[sbin[m] * D + o], sp[m] * hv);
        atomicAdd(&g_binQ[sbin[m] * D + o], sq[m] * hv);
    }
}

// =============== K3: bin-level prefix/suffix scan (smem-staged, fused) ===============
// NBCH=32 blocks x 256 threads; dyn smem = 2*BCH*64*4 + 2*BCH*4 = 66.5 KB
__global__ void k_binscan() {
    extern __shared__ float sm2[];
    float* sBP = sm2;                       // BCH*64
    float* sBQ = sm2 + BCH * 64;
    float* sdp = sm2 + 2 * BCH * 64;        // BCH
    float* sdq = sdp + BCH;
    __shared__ float sP[4][64], sQ[4][64], sw[8];

    int t = threadIdx.x;
    int chunk = blockIdx.x;
    int b0 = chunk * BCH;

    if (chunk == 0 && t == 0) {             // extrema consumed by K2; reset for next replay
        atomicExch(&g_encmax, 0u);
        atomicExch(&g_encmin, 0xFFFFFFFFu);
    }

    // stage this chunk's bin aggregates (coalesced float4, high MLP)
    {
        const float4* srcP = (const float4*)(g_binP + (size_t)b0 * D);
        const float4* srcQ = (const float4*)(g_binQ + (size_t)b0 * D);
        float4* dP = (float4*)sBP;
        float4* dQ = (float4*)sBQ;
#pragma unroll
        for (int i = t; i < BCH * 16; i += 256) { dP[i] = srcP[i]; dQ[i] = srcQ[i]; }
        if (t < BCH) { sdp[t] = g_bDp[b0 + t]; sdq[t] = g_bDq[b0 + t]; }
    }
    __syncthreads();

    // chunk sums
    int o = t & 63, r = t >> 6;
    float aP = 0.f, aQ = 0.f;
#pragma unroll 8
    for (int m = r; m < BCH; m += 4) { aP += sBP[m * 64 + o]; aQ += sBQ[m * 64 + o]; }
    sP[r][o] = aP; sQ[r][o] = aQ;

    float spv = 0.f, sqv = 0.f;
    if (t < BCH) { spv = sdp[t]; sqv = sdq[t]; }
#pragma unroll
    for (int s = 16; s; s >>= 1) {
        spv += __shfl_xor_sync(0xFFFFFFFFu, spv, s);
        sqv += __shfl_xor_sync(0xFFFFFFFFu, sqv, s);
    }
    if (t < BCH && (t & 31) == 0) { sw[t >> 5] = spv; sw[4 + (t >> 5)] = sqv; }
    __syncthreads();

    if (r == 0) {
        g_csumP[chunk * 64 + o] = sP[0][o] + sP[1][o] + sP[2][o] + sP[3][o];
        g_csumQ[chunk * 64 + o] = sQ[0][o] + sQ[1][o] + sQ[2][o] + sQ[3][o];
    }
    if (t == 0) {
        g_csp[chunk] = sw[0] + sw[1] + sw[2] + sw[3];
        g_csq[chunk] = sw[4] + sw[5] + sw[6] + sw[7];
    }

    // grid barrier (32 blocks, all resident)
    __syncthreads();
    __threadfence();
    if (t == 0) {
        atomicAdd(&g_c2, 1);
        while (atomicAdd(&g_c2, 0) < NBCH) __nanosleep(64);
    }
    __syncthreads();

    // walks
    if (t < 64) {
        float off = 0.f;
#pragma unroll
        for (int c = 0; c < NBCH; c++) {
            float v = __ldcg(&g_csumQ[c * 64 + t]);
            if (c < chunk) off += v;
        }
        float run = off;
#pragma unroll 8
        for (int m = 0; m < BCH; m++) {
            g_Cneg[(size_t)(b0 + m) * D + t] = run;
            run += sBQ[m * 64 + t];
        }
        if (chunk == NBCH - 1) g_Cneg[(size_t)NB * D + t] = run;
    } else if (t < 128) {
        int c0 = t - 64;
        float off = 0.f;
#pragma unroll
        for (int c = 0; c < NBCH; c++) {
            float v = __ldcg(&g_csumP[c * 64 + c0]);
            if (c > chunk) off += v;
        }
        float run = off;
        if (chunk == NBCH - 1) g_Cpos[(size_t)NB * D + c0] = 0.f;
#pragma unroll 8
        for (int m = BCH - 1; m >= 0; m--) {
            run += sBP[m * 64 + c0];
            g_Cpos[(size_t)(b0 + m) * D + c0] = run;
        }
    } else if (t == 128) {
        float off = 0.f;
#pragma unroll
        for (int c = 0; c < NBCH; c++) { float v = __ldcg(&g_csq[c]); if (c < chunk) off += v; }
        float run = off;
        for (int m = 0; m < BCH; m++) { g_Dneg[b0 + m] = run; run += sdq[m]; }
        if (chunk == NBCH - 1) g_Dneg[NB] = run;
    } else if (t == 129) {
        float off = 0.f;
#pragma unroll
        for (int c = 0; c < NBCH; c++) { float v = __ldcg(&g_csp[c]); if (c > chunk) off += v; }
        float run = off;
        if (chunk == NBCH - 1) g_Dpos[NB] = 0.f;
        for (int m = BCH - 1; m >= 0; m--) { run += sdp[m]; g_Dpos[b0 + m] = run; }
    }

    // replay-safe counter reset
    __syncthreads();
    if (t == 0) {
        int d = atomicAdd(&g_c2done, 1);
        if (d == NBCH - 1) { atomicExch(&g_c2, 0); atomicExch(&g_c2done, 0); }
    }
}

// =============== K4: per-row combine + exact boundary bin + ELU ===============
__global__ void k_out(float* __restrict__ out) {
    int t = threadIdx.x;                 // 256, 4 rows/block
    int row = blockIdx.x * 4 + (t >> 6);
    int o = t & 63;

    float f1 = g_f1[row];
    float fmax = g_fmax, fmin = g_fmin, scale = g_scale;
    float s0 = f1 + fmax;
    float m = (s0 >= 0.f) ? s0 : ALPHA * s0;     // row max of lrelu logits
    float A = expf(s0 - m);
    float B = expf(ALPHA * s0 - m);
    float thr = -f1;

    int b = bin_of(thr, fmin, scale);

    float num = A * g_Cpos[(size_t)(b + 1) * D + o] + B * g_Cneg[(size_t)b * D + o];
    float den = A * g_Dpos[b + 1] + B * g_Dneg[b];

    int cnt = g_cnt[b];
    if (cnt > CAP) cnt = CAP;
    for (int j = 0; j < cnt; j++) {      // exact compares within boundary bin
        int idx = g_mIdx[b * CAP + j];
        float f2j = g_mF2[b * CAP + j];
        float d = f2j - fmax;
        float hv = g_h[idx * D + o];
        if (f2j >= thr) { float w = A * expf(d);         num = fmaf(w, hv, num); den += w; }
        else            { float w = B * expf(ALPHA * d); num = fmaf(w, hv, num); den += w; }
    }

    float ret = num / den;
    out[row * D + o] = (ret > 0.f) ? ret : expm1f(ret);
}

// ---------------- launch ----------------
extern "C" void kernel_launch(void* const* d_in, const int* in_sizes, int n_in,
                              void* d_out, int out_size) {
    const float* x  = (const float*)d_in[0];
    const float* Wt = (const float*)d_in[1];
    const float* a1 = (const float*)d_in[2];
    const float* b1 = (const float*)d_in[3];
    const float* a2 = (const float*)d_in[4];
    const float* b2 = (const float*)d_in[5];
    float* out = (float*)d_out;

    const int smem_scan = (2 * BCH * 64 + 2 * BCH) * 4;   // 66.5 KB

    static bool attr_set = false;
    if (!attr_set) {
        cudaFuncSetAttribute(k_binscan, cudaFuncAttributeMaxDynamicSharedMemorySize, smem_scan);
        attr_set = true;
    }

    k_feat<<<128, 1024>>>(x, Wt, a1, b1, a2, b2);
    k_binagg<<<64, 256>>>();
    k_binscan<<<NBCH, 256, smem_scan>>>();
    k_out<<<2048, 256>>>(out);
}